// round 1
// baseline (speedup 1.0000x reference)
#include <cuda_runtime.h>
#include <cuda_bf16.h>
#include <cstdint>

#define HF 128
#define WF 192
#define NA 9
#define NTOT (HF*WF*NA)          // 221184
#define TOPN 6000
#define POSTN 300
#define NB 94                    // ceil(6016/64)
#define CAND_MAX 16384
#define SORT_M 16384

__constant__ float c_anchors[NA][4] = {
    {-84.f,  -40.f,  99.f,  55.f},
    {-176.f, -88.f,  191.f, 103.f},
    {-360.f, -184.f, 375.f, 199.f},
    {-56.f,  -56.f,  71.f,  71.f},
    {-120.f, -120.f, 135.f, 135.f},
    {-248.f, -248.f, 263.f, 263.f},
    {-36.f,  -80.f,  51.f,  95.f},
    {-80.f,  -168.f, 95.f,  183.f},
    {-168.f, -344.f, 183.f, 359.f}
};

__device__ unsigned long long g_keys[NTOT];
__device__ float4 g_boxes[NTOT];
__device__ unsigned int g_hist[65536];
__device__ unsigned int g_thresh;
__device__ unsigned int g_cand_count;
__device__ unsigned long long g_cand[CAND_MAX];
__device__ float4 g_top_boxes[TOPN];
__device__ int g_vld[TOPN];
__device__ unsigned long long g_mask[6016 * NB];

// ---------------- K1: decode + keys + histogram ----------------
__global__ void k_score_box(const float* __restrict__ scores,
                            const float* __restrict__ deltas,
                            const float* __restrict__ im_info) {
    int i = blockIdx.x * blockDim.x + threadIdx.x;
    if (i >= NTOT) return;
    int k = i / NA;
    int a = i - k * NA;
    // score/delta side: k = y*WF + x
    int yd = k / WF;
    int xd = k - yd * WF;
    // anchor/shift side: k = x*HF + y  (meshgrid 'ij' quirk)
    int xs = k >> 7;          // k / 128
    int ys = k & 127;         // k % 128

    const int HW = HF * WF;
    int base = yd * WF + xd;
    float sc = scores[(NA + a) * HW + base];
    float dx = deltas[(4*a + 0) * HW + base];
    float dy = deltas[(4*a + 1) * HW + base];
    float dw = deltas[(4*a + 2) * HW + base];
    float dh = deltas[(4*a + 3) * HW + base];

    float sx = 16.f * (float)xs;
    float sy = 16.f * (float)ys;
    float ax1 = c_anchors[a][0] + sx;
    float ay1 = c_anchors[a][1] + sy;
    float ax2 = c_anchors[a][2] + sx;
    float ay2 = c_anchors[a][3] + sy;

    float w = ax2 - ax1 + 1.f;
    float h = ay2 - ay1 + 1.f;
    float cx = ax1 + 0.5f * w;
    float cy = ay1 + 0.5f * h;

    float pcx = dx * w + cx;
    float pcy = dy * h + cy;
    float pw = expf(dw) * w;
    float ph = expf(dh) * h;

    float x1 = pcx - 0.5f * pw;
    float y1 = pcy - 0.5f * ph;
    float x2 = pcx + 0.5f * pw;
    float y2 = pcy + 0.5f * ph;

    float im0 = im_info[0], im1 = im_info[1], im2 = im_info[2];
    x1 = fminf(fmaxf(x1, 0.f), im1 - 1.f);
    x2 = fminf(fmaxf(x2, 0.f), im1 - 1.f);
    y1 = fminf(fmaxf(y1, 0.f), im0 - 1.f);
    y2 = fminf(fmaxf(y2, 0.f), im0 - 1.f);

    float ms = 16.f * im2;
    bool valid = (x2 - x1 + 1.f >= ms) && (y2 - y1 + 1.f >= ms);

    unsigned int srt;
    if (valid) {
        unsigned int b = __float_as_uint(sc);
        srt = (b & 0x80000000u) ? ~b : (b | 0x80000000u);
    } else {
        srt = 0x007FFFFFu;   // flip(-inf)
    }
    unsigned long long key = ((unsigned long long)srt << 32) | (0xFFFFFFFFu - (unsigned int)i);
    g_keys[i] = key;
    g_boxes[i] = make_float4(x1, y1, x2, y2);
    atomicAdd(&g_hist[srt >> 16], 1u);
}

// ---------------- K2: find top-6000 threshold bucket ----------------
__global__ void k_thresh() {
    __shared__ unsigned int s[256];
    __shared__ int gsel;
    __shared__ unsigned int above_s;
    int t = threadIdx.x;
    unsigned int sum = 0;
#pragma unroll 8
    for (int b = 0; b < 256; b++) sum += g_hist[t * 256 + b];
    s[t] = sum;
    __syncthreads();
    // suffix scan (Hillis-Steele)
    for (int off = 1; off < 256; off <<= 1) {
        unsigned int v = (t + off < 256) ? s[t + off] : 0u;
        __syncthreads();
        s[t] += v;
        __syncthreads();
    }
    unsigned int nxt = (t == 255) ? 0u : s[t + 1];
    if (s[t] >= TOPN && nxt < TOPN) { gsel = t; above_s = nxt; }
    __syncthreads();
    int g = gsel;
    unsigned int above = above_s;
    unsigned int fv = g_hist[g * 256 + t];
    __syncthreads();
    s[t] = fv;
    __syncthreads();
    for (int off = 1; off < 256; off <<= 1) {
        unsigned int v = (t + off < 256) ? s[t + off] : 0u;
        __syncthreads();
        s[t] += v;
        __syncthreads();
    }
    unsigned int nxt2 = (t == 255) ? 0u : s[t + 1];
    if (above + s[t] >= TOPN && above + nxt2 < TOPN) {
        g_thresh = (unsigned int)(g * 256 + t);
    }
}

// ---------------- K3: compact candidates ----------------
__global__ void k_compact() {
    int i = blockIdx.x * blockDim.x + threadIdx.x;
    if (i >= NTOT) return;
    unsigned long long key = g_keys[i];
    unsigned int bucket = (unsigned int)(key >> 48);
    if (bucket >= g_thresh) {
        unsigned int pos = atomicAdd(&g_cand_count, 1u);
        if (pos < CAND_MAX) g_cand[pos] = key;
    }
}

// ---------------- K4: bitonic sort + gather top-6000 ----------------
__global__ void k_sort() {
    extern __shared__ unsigned long long sk[];
    int tid = threadIdx.x;
    unsigned int cnt = g_cand_count;
    if (cnt > CAND_MAX) cnt = CAND_MAX;
    for (int j = tid; j < SORT_M; j += 1024)
        sk[j] = (j < (int)cnt) ? g_cand[j] : 0ull;
    __syncthreads();
    for (int k = 2; k <= SORT_M; k <<= 1) {
        for (int j = k >> 1; j > 0; j >>= 1) {
            for (int i = tid; i < SORT_M; i += 1024) {
                int ixj = i ^ j;
                if (ixj > i) {
                    bool desc = ((i & k) == 0);
                    unsigned long long va = sk[i], vb = sk[ixj];
                    if (desc ? (va < vb) : (va > vb)) { sk[i] = vb; sk[ixj] = va; }
                }
            }
            __syncthreads();
        }
    }
    for (int j = tid; j < TOPN; j += 1024) {
        unsigned long long key = sk[j];
        if (key != 0ull) {
            unsigned int idx = 0xFFFFFFFFu - (unsigned int)(key & 0xFFFFFFFFull);
            g_top_boxes[j] = g_boxes[idx];
            g_vld[j] = ((unsigned int)(key >> 32)) > 0x007FFFFFu;
        } else {
            g_top_boxes[j] = make_float4(0.f, 0.f, 0.f, 0.f);
            g_vld[j] = 0;
        }
    }
}

// ---------------- K5: NMS suppression bitmask ----------------
__global__ void k_mask() {
    int bi = blockIdx.y, bj = blockIdx.x;
    int t = threadIdx.x;
    int i = bi * 64 + t;
    if (bj < bi) {
        g_mask[i * NB + bj] = 0ull;
        return;
    }
    __shared__ float4 bb[64];
    __shared__ float ar[64];
    int jg0 = bj * 64 + t;
    if (jg0 < TOPN) {
        float4 b = g_top_boxes[jg0];
        bb[t] = b;
        ar[t] = (b.z - b.x) * (b.w - b.y);
    } else {
        bb[t] = make_float4(0.f, 0.f, 0.f, 0.f);
        ar[t] = 0.f;
    }
    __syncthreads();
    if (i >= TOPN) return;
    float4 bi_box = g_top_boxes[i];
    float area_i = (bi_box.z - bi_box.x) * (bi_box.w - bi_box.y);
    unsigned long long m = 0ull;
#pragma unroll 4
    for (int jj = 0; jj < 64; jj++) {
        int jg = bj * 64 + jj;
        float4 bj_box = bb[jj];
        float ix1 = fmaxf(bi_box.x, bj_box.x);
        float iy1 = fmaxf(bi_box.y, bj_box.y);
        float ix2 = fminf(bi_box.z, bj_box.z);
        float iy2 = fminf(bi_box.w, bj_box.w);
        float inter = fmaxf(ix2 - ix1, 0.f) * fmaxf(iy2 - iy1, 0.f);
        float denom = fmaxf(area_i + ar[jj] - inter, 1e-9f);
        float iou = inter / denom;
        if (iou > 0.7f && jg > i && jg < TOPN) m |= (1ull << jj);
    }
    g_mask[i * NB + bj] = m;
}

// ---------------- K6: sequential greedy collect (1 warp) ----------------
__global__ void k_collect(float* __restrict__ out) {
    __shared__ unsigned long long remv[NB];
    int lane = threadIdx.x;
    for (int t = lane; t < NB; t += 32) remv[t] = 0ull;
    __syncwarp();
    int kept = 0;
    bool done = false;
    for (int ib = 0; ib < NB && !done; ib++) {
        unsigned long long r = remv[ib];
        int lim = TOPN - ib * 64;
        if (lim > 64) lim = 64;
        for (int bit = 0; bit < lim; bit++) {
            if ((r >> bit) & 1ull) continue;
            int i = ib * 64 + bit;
            if (!g_vld[i]) continue;
            if (lane == 0) {
                float4 b = g_top_boxes[i];
                float* row = out + kept * 5;
                row[0] = 0.f; row[1] = b.x; row[2] = b.y; row[3] = b.z; row[4] = b.w;
            }
            kept++;
            if (kept >= POSTN) { done = true; break; }
            const unsigned long long* mrow = &g_mask[(size_t)i * NB];
            for (int t = lane; t < NB; t += 32) remv[t] |= mrow[t];
            __syncwarp();
            r = remv[ib];
        }
    }
}

extern "C" void kernel_launch(void* const* d_in, const int* in_sizes, int n_in,
                              void* d_out, int out_size) {
    const float* scores  = (const float*)d_in[0];
    const float* deltas  = (const float*)d_in[1];
    const float* im_info = (const float*)d_in[2];
    float* out = (float*)d_out;

    void* p;
    cudaGetSymbolAddress(&p, g_hist);
    cudaMemsetAsync(p, 0, 65536 * sizeof(unsigned int));
    cudaGetSymbolAddress(&p, g_cand_count);
    cudaMemsetAsync(p, 0, sizeof(unsigned int));
    cudaMemsetAsync(d_out, 0, POSTN * 5 * sizeof(float));

    k_score_box<<<(NTOT + 255) / 256, 256>>>(scores, deltas, im_info);
    k_thresh<<<1, 256>>>();
    k_compact<<<(NTOT + 255) / 256, 256>>>();
    cudaFuncSetAttribute(k_sort, cudaFuncAttributeMaxDynamicSharedMemorySize,
                         SORT_M * sizeof(unsigned long long));
    k_sort<<<1, 1024, SORT_M * sizeof(unsigned long long)>>>();
    dim3 gm(NB, NB);
    k_mask<<<gm, 64>>>();
    k_collect<<<1, 32>>>(out);
}

// round 2
// speedup vs baseline: 2.3980x; 2.3980x over previous
#include <cuda_runtime.h>
#include <cuda_bf16.h>
#include <cstdint>

#define HF 128
#define WF 192
#define NA 9
#define NTOT (HF*WF*NA)          // 221184
#define TOPN 6000
#define POSTN 300
#define NB 94                    // ceil(6000/64)
#define CAND_MAX 16384
#define RB 128                   // rank-kernel block threads
#define JCHUNKS 8
#define JCHUNK (CAND_MAX/JCHUNKS)

__constant__ float c_anchors[NA][4] = {
    {-84.f,  -40.f,  99.f,  55.f},
    {-176.f, -88.f,  191.f, 103.f},
    {-360.f, -184.f, 375.f, 199.f},
    {-56.f,  -56.f,  71.f,  71.f},
    {-120.f, -120.f, 135.f, 135.f},
    {-248.f, -248.f, 263.f, 263.f},
    {-36.f,  -80.f,  51.f,  95.f},
    {-80.f,  -168.f, 95.f,  183.f},
    {-168.f, -344.f, 183.f, 359.f}
};

__device__ unsigned long long g_keys[NTOT];
__device__ float4 g_boxes[NTOT];
__device__ unsigned int g_hist[65536];
__device__ unsigned int g_thresh;
__device__ unsigned int g_cand_count;
__device__ unsigned long long g_cand[CAND_MAX];
__device__ unsigned int g_rank[CAND_MAX];
__device__ float4 g_top_boxes[TOPN];
__device__ int g_vld[TOPN];
__device__ unsigned long long g_mask[6016 * NB];

// ---------------- K1: decode + keys + histogram ----------------
__global__ void k_score_box(const float* __restrict__ scores,
                            const float* __restrict__ deltas,
                            const float* __restrict__ im_info) {
    int i = blockIdx.x * blockDim.x + threadIdx.x;
    if (i >= NTOT) return;
    int k = i / NA;
    int a = i - k * NA;
    // score/delta side: k = y*WF + x
    int yd = k / WF;
    int xd = k - yd * WF;
    // anchor/shift side: k = x*HF + y  (meshgrid 'ij' quirk)
    int xs = k >> 7;
    int ys = k & 127;

    const int HW = HF * WF;
    int base = yd * WF + xd;
    float sc = scores[(NA + a) * HW + base];
    float dx = deltas[(4*a + 0) * HW + base];
    float dy = deltas[(4*a + 1) * HW + base];
    float dw = deltas[(4*a + 2) * HW + base];
    float dh = deltas[(4*a + 3) * HW + base];

    float sx = 16.f * (float)xs;
    float sy = 16.f * (float)ys;
    float ax1 = c_anchors[a][0] + sx;
    float ay1 = c_anchors[a][1] + sy;
    float ax2 = c_anchors[a][2] + sx;
    float ay2 = c_anchors[a][3] + sy;

    float w = ax2 - ax1 + 1.f;
    float h = ay2 - ay1 + 1.f;
    float cx = ax1 + 0.5f * w;
    float cy = ay1 + 0.5f * h;

    float pcx = dx * w + cx;
    float pcy = dy * h + cy;
    float pw = expf(dw) * w;
    float ph = expf(dh) * h;

    float x1 = pcx - 0.5f * pw;
    float y1 = pcy - 0.5f * ph;
    float x2 = pcx + 0.5f * pw;
    float y2 = pcy + 0.5f * ph;

    float im0 = im_info[0], im1 = im_info[1], im2 = im_info[2];
    x1 = fminf(fmaxf(x1, 0.f), im1 - 1.f);
    x2 = fminf(fmaxf(x2, 0.f), im1 - 1.f);
    y1 = fminf(fmaxf(y1, 0.f), im0 - 1.f);
    y2 = fminf(fmaxf(y2, 0.f), im0 - 1.f);

    float ms = 16.f * im2;
    bool valid = (x2 - x1 + 1.f >= ms) && (y2 - y1 + 1.f >= ms);

    unsigned int srt;
    if (valid) {
        unsigned int b = __float_as_uint(sc);
        srt = (b & 0x80000000u) ? ~b : (b | 0x80000000u);
    } else {
        srt = 0x007FFFFFu;   // flip(-inf)
    }
    unsigned long long key = ((unsigned long long)srt << 32) | (0xFFFFFFFFu - (unsigned int)i);
    g_keys[i] = key;
    g_boxes[i] = make_float4(x1, y1, x2, y2);
    atomicAdd(&g_hist[srt >> 16], 1u);
}

// ---------------- K2: find top-6000 threshold bucket ----------------
__global__ void k_thresh() {
    __shared__ unsigned int s[256];
    __shared__ int gsel;
    __shared__ unsigned int above_s;
    int t = threadIdx.x;
    unsigned int sum = 0;
#pragma unroll 8
    for (int b = 0; b < 256; b++) sum += g_hist[t * 256 + b];
    s[t] = sum;
    __syncthreads();
    for (int off = 1; off < 256; off <<= 1) {
        unsigned int v = (t + off < 256) ? s[t + off] : 0u;
        __syncthreads();
        s[t] += v;
        __syncthreads();
    }
    unsigned int nxt = (t == 255) ? 0u : s[t + 1];
    if (s[t] >= TOPN && nxt < TOPN) { gsel = t; above_s = nxt; }
    __syncthreads();
    int g = gsel;
    unsigned int above = above_s;
    unsigned int fv = g_hist[g * 256 + t];
    __syncthreads();
    s[t] = fv;
    __syncthreads();
    for (int off = 1; off < 256; off <<= 1) {
        unsigned int v = (t + off < 256) ? s[t + off] : 0u;
        __syncthreads();
        s[t] += v;
        __syncthreads();
    }
    unsigned int nxt2 = (t == 255) ? 0u : s[t + 1];
    if (above + s[t] >= TOPN && above + nxt2 < TOPN) {
        g_thresh = (unsigned int)(g * 256 + t);
    }
}

// ---------------- K3: compact candidates ----------------
__global__ void k_compact() {
    int i = blockIdx.x * blockDim.x + threadIdx.x;
    if (i >= NTOT) return;
    unsigned long long key = g_keys[i];
    unsigned int bucket = (unsigned int)(key >> 48);
    if (bucket >= g_thresh) {
        unsigned int pos = atomicAdd(&g_cand_count, 1u);
        if (pos < CAND_MAX) g_cand[pos] = key;
    }
}

// ---------------- K4a: exact rank by counting (keys unique) ----------------
__global__ void k_rank() {
    __shared__ unsigned long long sk[256];
    unsigned int C = g_cand_count;
    if (C > CAND_MAX) C = CAND_MAX;
    if (blockIdx.x * RB >= C) return;            // uniform per block
    int i = blockIdx.x * RB + threadIdx.x;
    unsigned long long mykey = (i < (int)C) ? g_cand[i] : 0ull;
    int jbeg = blockIdx.y * JCHUNK;
    int jend = jbeg + JCHUNK;
    if (jend > (int)C) jend = (int)C;
    unsigned int cnt = 0;
    for (int t0 = jbeg; t0 < jend; t0 += 256) {
        int n = jend - t0; if (n > 256) n = 256;
        for (int t = threadIdx.x; t < n; t += RB) sk[t] = g_cand[t0 + t];
        __syncthreads();
#pragma unroll 8
        for (int t = 0; t < n; t++) cnt += (sk[t] > mykey) ? 1u : 0u;
        __syncthreads();
    }
    if (i < (int)C && cnt) atomicAdd(&g_rank[i], cnt);
}

// ---------------- K4b: scatter boxes to their rank slot ----------------
__global__ void k_scatter() {
    unsigned int C = g_cand_count;
    if (C > CAND_MAX) C = CAND_MAX;
    int i = blockIdx.x * blockDim.x + threadIdx.x;
    if (i >= (int)C) return;
    unsigned int r = g_rank[i];
    if (r < TOPN) {
        unsigned long long key = g_cand[i];
        unsigned int idx = 0xFFFFFFFFu - (unsigned int)(key & 0xFFFFFFFFull);
        g_top_boxes[r] = g_boxes[idx];
        g_vld[r] = ((unsigned int)(key >> 32)) > 0x007FFFFFu;
    }
}

// ---------------- K5: NMS suppression bitmask (upper triangle only) ----------------
__global__ void k_mask() {
    int bi = blockIdx.y, bj = blockIdx.x;
    if (bj < bi) return;                          // lower triangle never read
    int t = threadIdx.x;
    int i = bi * 64 + t;
    __shared__ float4 bb[64];
    __shared__ float ar[64];
    int jg0 = bj * 64 + t;
    if (jg0 < TOPN) {
        float4 b = g_top_boxes[jg0];
        bb[t] = b;
        ar[t] = (b.z - b.x) * (b.w - b.y);
    } else {
        bb[t] = make_float4(0.f, 0.f, 0.f, 0.f);
        ar[t] = 0.f;
    }
    __syncthreads();
    if (i >= TOPN) return;
    float4 bi_box = g_top_boxes[i];
    float area_i = (bi_box.z - bi_box.x) * (bi_box.w - bi_box.y);
    unsigned long long m = 0ull;
#pragma unroll 4
    for (int jj = 0; jj < 64; jj++) {
        int jg = bj * 64 + jj;
        float4 bj_box = bb[jj];
        float ix1 = fmaxf(bi_box.x, bj_box.x);
        float iy1 = fmaxf(bi_box.y, bj_box.y);
        float ix2 = fminf(bi_box.z, bj_box.z);
        float iy2 = fminf(bi_box.w, bj_box.w);
        float inter = fmaxf(ix2 - ix1, 0.f) * fmaxf(iy2 - iy1, 0.f);
        float denom = fmaxf(area_i + ar[jj] - inter, 1e-9f);
        float iou = inter / denom;
        if (iou > 0.7f && jg > i && jg < TOPN) m |= (1ull << jj);
    }
    g_mask[(size_t)i * NB + bj] = m;
}

// ---------------- K6: block-staged greedy collect ----------------
// Uniform control flow across the whole block (all branch data identical per
// thread), so __syncthreads inside the scan is legal.
__global__ void k_collect(float* __restrict__ out) {
    extern __shared__ unsigned long long sh[];
    unsigned long long* remv = sh;          // [NB]
    unsigned long long* tile = sh + NB;     // [64 * NB]
    int tid = threadIdx.x;                  // 1024 threads
    for (int t = tid; t < NB; t += 1024) remv[t] = 0ull;
    __syncthreads();

    int kept = 0;
    for (int ib = 0; ib < NB; ib++) {
        int rows = TOPN - ib * 64; if (rows > 64) rows = 64;
        int wcnt = NB - ib;
        int total = rows * wcnt;
        // cooperative load of this block's (upper-triangle) mask rows
        for (int t = tid; t < total; t += 1024) {
            int r = t / wcnt;
            int w = t - r * wcnt;
            tile[r * NB + w] = g_mask[(size_t)(ib * 64 + r) * NB + ib + w];
        }
        __syncthreads();

        unsigned long long rcur = remv[ib];
        for (int bit = 0; bit < rows; bit++) {
            if ((rcur >> bit) & 1ull) continue;
            int i = ib * 64 + bit;
            if (!g_vld[i]) continue;
            if (tid == 0) {
                float4 b = g_top_boxes[i];
                float* row = out + kept * 5;
                row[0] = 0.f; row[1] = b.x; row[2] = b.y; row[3] = b.z; row[4] = b.w;
            }
            kept++;
            if (kept >= POSTN) return;
            for (int t = tid; t < wcnt; t += 1024)
                remv[ib + t] |= tile[bit * NB + t];
            __syncthreads();
            rcur = remv[ib];
        }
        __syncthreads();   // protect tile before next iteration's overwrite
    }
}

extern "C" void kernel_launch(void* const* d_in, const int* in_sizes, int n_in,
                              void* d_out, int out_size) {
    const float* scores  = (const float*)d_in[0];
    const float* deltas  = (const float*)d_in[1];
    const float* im_info = (const float*)d_in[2];
    float* out = (float*)d_out;

    void* p;
    cudaGetSymbolAddress(&p, g_hist);
    cudaMemsetAsync(p, 0, 65536 * sizeof(unsigned int));
    cudaGetSymbolAddress(&p, g_cand_count);
    cudaMemsetAsync(p, 0, sizeof(unsigned int));
    cudaGetSymbolAddress(&p, g_rank);
    cudaMemsetAsync(p, 0, CAND_MAX * sizeof(unsigned int));
    cudaMemsetAsync(d_out, 0, POSTN * 5 * sizeof(float));

    k_score_box<<<(NTOT + 255) / 256, 256>>>(scores, deltas, im_info);
    k_thresh<<<1, 256>>>();
    k_compact<<<(NTOT + 255) / 256, 256>>>();

    dim3 gr(CAND_MAX / RB, JCHUNKS);
    k_rank<<<gr, RB>>>();
    k_scatter<<<CAND_MAX / 256, 256>>>();

    dim3 gm(NB, NB);
    k_mask<<<gm, 64>>>();

    size_t csh = (size_t)(NB + 64 * NB) * sizeof(unsigned long long);
    cudaFuncSetAttribute(k_collect, cudaFuncAttributeMaxDynamicSharedMemorySize, (int)csh);
    k_collect<<<1, 1024, csh>>>(out);
}